// round 13
// baseline (speedup 1.0000x reference)
#include <cuda_runtime.h>
#include <math.h>
#include <stdint.h>

#define BATCH 8
#define TOTAL 21824
#define DETS  100
#define IMGF  1024.0f
#define STH   0.2f
#define NMST  0.6f
#define MAXB  128    // per-class bucket capacity (mean ~41, 13-sigma safe)
#define BINN  4096   // quantization bins
#define BCAP  512    // boundary-bin capacity (expected ~16)
#define OCAP  1024   // out contention capacity (expected ~110)
#define SCAP  3328   // survivor capacity per batch (max possible 3320)

// ---------------- scratch (zero at module load; zeroing restored each call) ----------
__device__ unsigned long long d_keys[BATCH * TOTAL];
__device__ unsigned long long d_bucket[BATCH * 80 * MAXB];
__device__ int                d_ccnt[BATCH * 80];
__device__ int                d_hist[BATCH * 3 * BINN];   // levels 0..2 select hist

__device__ __forceinline__ float sigf(float x) { return 1.0f / (1.0f + expf(-x)); }

__device__ __forceinline__ float key_score_hi(unsigned h) {
    unsigned uo = ~h;
    unsigned bits = (uo & 0x80000000u) ? (uo ^ 0x80000000u) : (~uo);
    return __uint_as_float(bits);
}
__device__ __forceinline__ float key_score(unsigned long long key) {
    return key_score_hi((unsigned)(key >> 32));
}
// monotone: higher score -> higher bin; masked (-1) -> bin 0
__device__ __forceinline__ int qbin(unsigned h) {
    float s = key_score_hi(h);
    return (s > 0.0f) ? min(BINN - 1, (int)(s * (float)BINN)) : 0;
}

__device__ __forceinline__ void bucket_push(int b, unsigned long long key) {
    int c = (int)(key & 127ULL);
    int pos = atomicAdd(&d_ccnt[b * 80 + c], 1);
    if (pos < MAXB) d_bucket[(size_t)(b * 80 + c) * MAXB + pos] = key;
}

#define CP_ASYNC16(sm_u32, gptr) \
    asm volatile("cp.async.cg.shared.global [%0], [%1], 16;" :: "r"(sm_u32), "l"(gptr))
#define CP_COMMIT() asm volatile("cp.async.commit_group;")

// ---------------- K1: cp.async 2-tile pipelined score + argmax + hist/push -------------
// key = (~orderable(score))<<32 | idx<<7 | label : ascending == (score desc, idx asc);
// keys globally distinct; matches jax.lax.top_k stable tie order.
// Levels 0-2: feed the per-(batch,level) quantized histogram (used by k_select).
// Levels 3-4 (k >= n, everything selected): push straight into class buckets here.
#define SCORE_SMEM (81920 + 1024)

__global__ __launch_bounds__(512) void k_score(const float* __restrict__ logits,
                                               const float* __restrict__ ctr) {
    extern __shared__ float4 s4[];   // 2 tiles x 2560 float4, then 256 ctr floats
    float* ctr_s = (float*)((char*)s4 + 81920);
    int tid = threadIdx.x;
    size_t tile0 = (size_t)blockIdx.x * 2;
    const float4* g = reinterpret_cast<const float4*>(logits) + tile0 * 2560;
    unsigned sbase = (unsigned)__cvta_generic_to_shared(s4);

#pragma unroll
    for (int i = 0; i < 5; i++) {
        int off = i * 512 + tid;
        CP_ASYNC16(sbase + off * 16, g + off);
    }
    if (tid < 64) CP_ASYNC16(sbase + 81920 + tid * 16, ctr + tile0 * 128 + tid * 4);
    CP_COMMIT();
#pragma unroll
    for (int i = 0; i < 5; i++) {
        int off = 2560 + i * 512 + tid;
        CP_ASYNC16(sbase + off * 16, g + off);
    }
    CP_COMMIT();

    int la = tid >> 2;   // local anchor 0..127
    int q  = tid & 3;    // quarter: cols 20q..20q+19

#pragma unroll
    for (int s = 0; s < 2; s++) {
        if (s == 0) asm volatile("cp.async.wait_group 1;");
        else        asm volatile("cp.async.wait_group 0;");
        __syncthreads();

        const float4* rowq = s4 + s * 2560 + la * 20 + q * 5;
        float best = -1e30f;
        int bi = 0;
#pragma unroll
        for (int i = 0; i < 5; i++) {  // strict > keeps first-max within lane
            float4 v = rowq[i];
            int cb = q * 20 + i * 4;
            if (v.x > best) { best = v.x; bi = cb + 0; }
            if (v.y > best) { best = v.y; bi = cb + 1; }
            if (v.z > best) { best = v.z; bi = cb + 2; }
            if (v.w > best) { best = v.w; bi = cb + 3; }
        }
#pragma unroll
        for (int o = 2; o >= 1; o >>= 1) {  // tie -> lower column (= first occurrence)
            float ov = __shfl_down_sync(0xFFFFFFFFu, best, o);
            int   oc = __shfl_down_sync(0xFFFFFFFFu, bi, o);
            if (ov > best || (ov == best && oc < bi)) { best = ov; bi = oc; }
        }
        if (q == 0) {
            int ga = (int)(tile0 + s) * 128 + la;
            float sc = sqrtf(sigf(best) * sigf(ctr_s[s * 128 + la]));
            float smv = (sc > STH) ? sc : -1.0f;
            unsigned u = __float_as_uint(smv);
            u ^= (u & 0x80000000u) ? 0xFFFFFFFFu : 0x80000000u;
            unsigned h = ~u;
            int b = ga / TOTAL;
            int i_loc = ga - b * TOTAL;
            unsigned long long key = ((unsigned long long)h << 32) |
                                     ((unsigned)(i_loc << 7) | (unsigned)bi);
            if (i_loc >= 21504) {           // levels 3,4: selected unconditionally
                bucket_push(b, key);
            } else {
                d_keys[ga] = key;
                int lvl = (i_loc < 16384) ? 0 : (i_loc < 20480) ? 1 : 2;
                atomicAdd(&d_hist[(b * 3 + lvl) * BINN + qbin(h)], 1);
            }
        }
        __syncthreads();
    }
}

// ---------------- K2: per (batch, level 0..2) exact top-k; hist prebuilt ---------------
__global__ __launch_bounds__(1024, 1) void k_select() {
    const int LOFF[3] = {0, 16384, 20480};
    const int LN[3]   = {16384, 4096, 1024};
    const int LK[3]   = {1000, 1000, 1000};

    int b = blockIdx.x / 3, lvl = blockIdx.x % 3;
    int off = LOFF[lvl], n = LN[lvl], k = LK[lvl];
    int tid = threadIdx.x, lane = tid & 31, wid = tid >> 5;
    const unsigned long long* kp = d_keys + b * TOTAL + off;

    __shared__ unsigned long long binkeys[BCAP];
    __shared__ int warpsum[32];
    __shared__ int sh_Q, sh_kneed, sh_bc;
    if (tid == 0) sh_bc = 0;
    __syncthreads();

    const int* hist = d_hist + (b * 3 + lvl) * BINN;

    // descending-bin cumulative scan (4 bins/thread): boundary bin Q, kneed
    {
        int vv[4], mysum = 0;
#pragma unroll
        for (int j = 0; j < 4; j++) { vv[j] = hist[BINN - 1 - (tid * 4 + j)]; mysum += vv[j]; }
        int inc = mysum;
#pragma unroll
        for (int o = 1; o < 32; o <<= 1) { int t2 = __shfl_up_sync(0xFFFFFFFFu, inc, o); if (lane >= o) inc += t2; }
        if (lane == 31) warpsum[wid] = inc;
        __syncthreads();
        if (tid < 32) {
            int w = warpsum[tid], s = w;
#pragma unroll
            for (int o = 1; o < 32; o <<= 1) { int t2 = __shfl_up_sync(0xFFFFFFFFu, s, o); if (tid >= o) s += t2; }
            warpsum[tid] = s - w;  // exclusive
        }
        __syncthreads();
        int c = warpsum[wid] + inc - mysum;
#pragma unroll
        for (int j = 0; j < 4; j++) {
            if (c < k && c + vv[j] >= k) {
                sh_Q = BINN - 1 - (tid * 4 + j);
                sh_kneed = k - c;
            }
            c += vv[j];
        }
    }
    __syncthreads();
    int Q = sh_Q, kneed = sh_kneed;

    // single sweep: push bins > Q to class buckets; collect boundary bin
    for (int i = tid; i < n; i += 1024) {
        unsigned long long key = kp[i];
        int q = qbin((unsigned)(key >> 32));
        if (q > Q) {
            bucket_push(b, key);
        } else if (q == Q) {
            int p = atomicAdd(&sh_bc, 1);
            if (p < BCAP) binkeys[p] = key;
        }
    }
    __syncthreads();
    int C = min(sh_bc, BCAP);

    // exact in-bin rank; push the kneed smallest boundary keys (keys distinct)
    for (int t = tid; t < C; t += 1024) {
        unsigned long long mk = binkeys[t];
        int r = 0;
        for (int j2 = 0; j2 < C; j2++) r += (binkeys[j2] < mk);
        if (r < kneed) bucket_push(b, mk);
    }
}

// ---------------- K3: per-batch NMS (warp/class) + top-100, all in SMEM ---------------
// 8 blocks x 1024 threads. Phase N: warp w handles classes w, w+32, w+64 -> survivors
// appended to SMEM + SMEM histogram. Phase O: quantized-bin cutoff + exact rank + write.
#define WSTRIDE   4352                          // kb 1024 | bxs 2048 | ar 512 | sv 512 | rm 128 (+pad)
#define OFF_SUR   (32 * WSTRIDE)                // 139264
#define OFF_HIST  (OFF_SUR + SCAP * 8)          // 165888
#define OFF_CONT  (OFF_HIST + BINN * 4)         // 182272
#define POST_SMEM (OFF_CONT + OCAP * 8)         // 190464

__global__ __launch_bounds__(1024, 1) void k_post(const float* __restrict__ reg,
                                                  const float* __restrict__ anchors,
                                                  float* __restrict__ out) {
    extern __shared__ unsigned char sm[];
    unsigned long long* survivors = (unsigned long long*)(sm + OFF_SUR);
    int* shist = (int*)(sm + OFF_HIST);
    unsigned long long* cont = (unsigned long long*)(sm + OFF_CONT);
    __shared__ unsigned long long win[DETS];
    __shared__ int warpsum[32];
    __shared__ int sh_sur, sh_cc, sh_Q;

    int b = blockIdx.x, tid = threadIdx.x, lane = tid & 31, wid = tid >> 5;

    for (int i = tid; i < BINN; i += 1024) shist[i] = 0;
    if (tid == 0) { sh_sur = 0; sh_cc = 0; sh_Q = 0; }
    __syncthreads();

    // ---------------- phase N: per-class NMS, one warp per class ----------------
    {
        unsigned char* wbase = sm + wid * WSTRIDE;
        unsigned long long* kb = (unsigned long long*)wbase;
        float4* bxs = (float4*)(wbase + 1024);
        float*  ar  = (float*)(wbase + 3072);
        float*  sv  = (float*)(wbase + 3584);
        unsigned char* rm = wbase + 4096;

        for (int c = wid; c < 80; c += 32) {
            int bc = b * 80 + c;
            int cnt = min(d_ccnt[bc], MAXB);
            if (cnt == 0) continue;
            for (int i = lane; i < cnt; i += 32)
                kb[i] = d_bucket[(size_t)bc * MAXB + i];
            __syncwarp();

            // warp bitonic sort ascending (== score desc, idx asc)
            int m = 2; while (m < cnt) m <<= 1;
            for (int i = lane; i < m; i += 32) if (i >= cnt) kb[i] = ~0ULL;
            __syncwarp();
            for (int kk = 2; kk <= m; kk <<= 1)
                for (int jj = kk >> 1; jj > 0; jj >>= 1) {
                    for (int cc = lane; cc < (m >> 1); cc += 32) {
                        int i1 = ((cc & ~(jj - 1)) << 1) | (cc & (jj - 1));
                        int l1 = i1 | jj;
                        bool up = ((i1 & kk) == 0);
                        unsigned long long a2 = kb[i1], d2 = kb[l1];
                        if ((a2 > d2) == up) { kb[i1] = d2; kb[l1] = a2; }
                    }
                    __syncwarp();
                }

            // decode
            for (int i = lane; i < cnt; i += 32) {
                unsigned long long key = kb[i];
                int idx = (int)((key >> 7) & 0x7FFFULL);
                sv[i] = key_score(key);
                rm[i] = 0;
                float4 an = reinterpret_cast<const float4*>(anchors)[idx];
                float cx = (an.x + an.z) * 0.5f, cy = (an.y + an.w) * 0.5f;
                float4 r = reinterpret_cast<const float4*>(reg)[(size_t)b * TOTAL + idx];
                float x1 = fminf(fmaxf(cx - r.x, 0.0f), IMGF);
                float y1 = fminf(fmaxf(cy - r.y, 0.0f), IMGF);
                float x2 = fminf(fmaxf(cx + r.z, 0.0f), IMGF);
                float y2 = fminf(fmaxf(cy + r.w, 0.0f), IMGF);
                bxs[i] = make_float4(x1, y1, x2, y2);
                ar[i] = fmaxf(x2 - x1, 0.0f) * fmaxf(y2 - y1, 0.0f);
            }
            __syncwarp();

            // greedy NMS (masked sort last; suppressed never suppress)
            for (int i = 0; i < cnt; i++) {
                if (sv[i] <= STH) break;
                if (rm[i]) continue;
                float4 bi = bxs[i];
                float ai = ar[i];
                for (int j = i + 1 + lane; j < cnt; j += 32) {
                    float4 bj = bxs[j];
                    float iw = fmaxf(fminf(bi.z, bj.z) - fmaxf(bi.x, bj.x), 0.0f);
                    float ih = fmaxf(fminf(bi.w, bj.w) - fmaxf(bi.y, bj.y), 0.0f);
                    float inter = iw * ih;
                    float iou = inter / fmaxf(ai + ar[j] - inter, 1e-9f);
                    if (iou > NMST) rm[j] = 1;
                }
                __syncwarp();
            }

            // append survivors (per-class cap DETS) to SMEM list + SMEM hist
            int wcnt = 0;
            for (int base = 0; base < cnt; base += 32) {
                int i = base + lane;
                bool acc = (i < cnt) && (sv[i] > STH) && !rm[i];
                unsigned bal = __ballot_sync(0xFFFFFFFFu, acc);
                int nb = __popc(bal);
                int nTake = min(nb, max(0, DETS - wcnt));
                int pos = 0;
                if (lane == 0 && nTake > 0) pos = atomicAdd(&sh_sur, nTake);
                pos = __shfl_sync(0xFFFFFFFFu, pos, 0);
                int rk = __popc(bal & ((1u << lane) - 1));
                if (acc && rk < nTake && pos + rk < SCAP) {
                    survivors[pos + rk] = kb[i];
                    atomicAdd(&shist[qbin((unsigned)(kb[i] >> 32))], 1);
                }
                wcnt += nb;
            }
        }
    }
    __syncthreads();

    // ---------------- phase O: top-100 of survivors ----------------
    int S = min(sh_sur, SCAP);
    int ns = min(DETS, S);

    if (ns > 0) {
        // descending-bin scan: first bin where cum >= ns
        int vv[4], mysum = 0;
#pragma unroll
        for (int j = 0; j < 4; j++) { vv[j] = shist[BINN - 1 - (tid * 4 + j)]; mysum += vv[j]; }
        int inc = mysum;
#pragma unroll
        for (int o = 1; o < 32; o <<= 1) { int t2 = __shfl_up_sync(0xFFFFFFFFu, inc, o); if (lane >= o) inc += t2; }
        if (lane == 31) warpsum[wid] = inc;
        __syncthreads();
        if (tid < 32) {
            int w = warpsum[tid], s = w;
#pragma unroll
            for (int o = 1; o < 32; o <<= 1) { int t2 = __shfl_up_sync(0xFFFFFFFFu, s, o); if (tid >= o) s += t2; }
            warpsum[tid] = s - w;
        }
        __syncthreads();
        int c = warpsum[wid] + inc - mysum;
#pragma unroll
        for (int j = 0; j < 4; j++) {
            if (c < ns && c + vv[j] >= ns) sh_Q = BINN - 1 - (tid * 4 + j);
            c += vv[j];
        }
        __syncthreads();
        int Q = sh_Q;

        // contention = all bins >= Q (superset of top-ns), from SMEM survivors
        for (int i = tid; i < S; i += 1024) {
            unsigned long long key = survivors[i];
            if (qbin((unsigned)(key >> 32)) >= Q) {
                int p = atomicAdd(&sh_cc, 1);
                if (p < OCAP) cont[p] = key;
            }
        }
        __syncthreads();
        int C = min(sh_cc, OCAP);

        // exact rank within contention == global rank for r < ns
        for (int t = tid; t < C; t += 1024) {
            unsigned long long mk = cont[t];
            int r = 0;
            for (int q2 = 0; q2 < C; q2++) r += (cont[q2] < mk);
            if (r < ns) win[r] = mk;
        }
    }
    __syncthreads();

    // decode + write
    for (int t = tid; t < DETS; t += 1024) {
        float* ob = out + ((size_t)b * DETS + t) * 4;
        if (t >= ns) {
            ob[0] = 0.0f; ob[1] = 0.0f; ob[2] = 0.0f; ob[3] = 0.0f;
            out[BATCH * DETS * 4 + b * DETS + t] = 0.0f;
            out[BATCH * DETS * 5 + b * DETS + t] = -1.0f;
        } else {
            unsigned long long key = win[t];
            int idx = (int)((key >> 7) & 0x7FFFULL);
            float4 an = reinterpret_cast<const float4*>(anchors)[idx];
            float cx = (an.x + an.z) * 0.5f, cy = (an.y + an.w) * 0.5f;
            float4 r = reinterpret_cast<const float4*>(reg)[(size_t)b * TOTAL + idx];
            float x1 = fminf(fmaxf(cx - r.x, 0.0f), IMGF);
            float y1 = fminf(fmaxf(cy - r.y, 0.0f), IMGF);
            float x2 = fminf(fmaxf(cx + r.z, 0.0f), IMGF);
            float y2 = fminf(fmaxf(cy + r.w, 0.0f), IMGF);
            ob[0] = x1; ob[1] = y1; ob[2] = x2; ob[3] = y2;
            out[BATCH * DETS * 4 + b * DETS + t] = key_score(key);
            out[BATCH * DETS * 5 + b * DETS + t] = (float)(key & 127ULL);
        }
    }
    __syncthreads();

    // restore per-batch scratch to zero for the next call
    for (int i = tid; i < 3 * BINN; i += 1024) d_hist[b * 3 * BINN + i] = 0;
    for (int i = tid; i < 80; i += 1024) d_ccnt[b * 80 + i] = 0;
}

// ---------------- launch ----------------
extern "C" void kernel_launch(void* const* d_in, const int* in_sizes, int n_in,
                              void* d_out, int out_size) {
    const float* logits  = (const float*)d_in[0];  // (8, 21824, 80)
    const float* reg     = (const float*)d_in[1];  // (8, 21824, 4)
    const float* ctr     = (const float*)d_in[2];  // (8, 21824, 1)
    const float* anchors = (const float*)d_in[3];  // (21824, 4)
    float* out = (float*)d_out;

    cudaFuncSetAttribute(k_score, cudaFuncAttributeMaxDynamicSharedMemorySize, SCORE_SMEM);
    cudaFuncSetAttribute(k_post, cudaFuncAttributeMaxDynamicSharedMemorySize, POST_SMEM);

    k_score<<<(BATCH * TOTAL) / 256, 512, SCORE_SMEM>>>(logits, ctr);
    k_select<<<BATCH * 3, 1024>>>();
    k_post<<<BATCH, 1024, POST_SMEM>>>(reg, anchors, out);
}

// round 14
// speedup vs baseline: 1.2523x; 1.2523x over previous
#include <cuda_runtime.h>
#include <math.h>
#include <stdint.h>

#define BATCH 8
#define TOTAL 21824
#define DETS  100
#define IMGF  1024.0f
#define STH   0.2f
#define NMST  0.6f
#define MAXB  128    // per-class bucket capacity (mean ~41, 13-sigma safe)
#define BINN  4096   // quantization bins
#define BCAP  512    // boundary-bin capacity (expected ~16)
#define OCAP  1024   // out contention capacity (expected ~110)
#define SCAP  3328   // compact survivor capacity per batch (max possible 3320)

// ---------------- scratch (zero at module load; zeroing restored each call) ----------
__device__ unsigned long long d_keys[BATCH * TOTAL];
__device__ unsigned long long d_bucket[BATCH * 80 * MAXB];
__device__ int                d_ccnt[BATCH * 80];
__device__ unsigned long long d_sur[BATCH * SCAP];
__device__ int                d_surtot[BATCH];
__device__ int                d_hist[BATCH * 3 * BINN];   // levels 0..2 select hist
__device__ int                d_ohist[BATCH * BINN];      // survivor hist

__device__ __forceinline__ float sigf(float x) { return 1.0f / (1.0f + expf(-x)); }

__device__ __forceinline__ float key_score_hi(unsigned h) {
    unsigned uo = ~h;
    unsigned bits = (uo & 0x80000000u) ? (uo ^ 0x80000000u) : (~uo);
    return __uint_as_float(bits);
}
__device__ __forceinline__ float key_score(unsigned long long key) {
    return key_score_hi((unsigned)(key >> 32));
}
// monotone: higher score -> higher bin; masked (-1) -> bin 0
__device__ __forceinline__ int qbin(unsigned h) {
    float s = key_score_hi(h);
    return (s > 0.0f) ? min(BINN - 1, (int)(s * (float)BINN)) : 0;
}

__device__ __forceinline__ void bucket_push(int b, unsigned long long key) {
    int c = (int)(key & 127ULL);
    int pos = atomicAdd(&d_ccnt[b * 80 + c], 1);
    if (pos < MAXB) d_bucket[(size_t)(b * 80 + c) * MAXB + pos] = key;
}

// ---------------- K1: staged coalesced score + argmax -> key / hist / push ------------
// key = (~orderable(score))<<32 | idx<<7 | label : ascending == (score desc, idx asc);
// keys globally distinct; matches jax.lax.top_k stable tie order.
// Levels 0-2: store key + feed per-(batch,level) quantized hist (used by k_select).
// Levels 3-4 (k >= n): selected unconditionally -> push straight into class buckets.
__global__ __launch_bounds__(512) void k_score(const float* __restrict__ logits,
                                               const float* __restrict__ ctr) {
    __shared__ float4 s4[128 * 20];  // 40 KB
    int tid = threadIdx.x;
    const float4* g = reinterpret_cast<const float4*>(logits) + (size_t)blockIdx.x * (128 * 20);
#pragma unroll
    for (int i = 0; i < 5; i++) s4[i * 512 + tid] = __ldcs(&g[i * 512 + tid]);
    __syncthreads();

    int la = tid >> 2;   // local anchor 0..127
    int q  = tid & 3;    // quarter: cols 20q..20q+19
    const float4* rowq = s4 + la * 20 + q * 5;
    float best = -1e30f;
    int bi = 0;
#pragma unroll
    for (int i = 0; i < 5; i++) {  // strict > keeps first-max within lane
        float4 v = rowq[i];
        int cb = q * 20 + i * 4;
        if (v.x > best) { best = v.x; bi = cb + 0; }
        if (v.y > best) { best = v.y; bi = cb + 1; }
        if (v.z > best) { best = v.z; bi = cb + 2; }
        if (v.w > best) { best = v.w; bi = cb + 3; }
    }
#pragma unroll
    for (int o = 2; o >= 1; o >>= 1) {  // tie -> lower column (= first occurrence)
        float ov = __shfl_down_sync(0xFFFFFFFFu, best, o);
        int   oc = __shfl_down_sync(0xFFFFFFFFu, bi, o);
        if (ov > best || (ov == best && oc < bi)) { best = ov; bi = oc; }
    }
    if (q == 0) {
        int ga = blockIdx.x * 128 + la;   // BATCH*TOTAL % 128 == 0
        float sc = sqrtf(sigf(best) * sigf(__ldg(&ctr[ga])));
        float smv = (sc > STH) ? sc : -1.0f;
        unsigned u = __float_as_uint(smv);
        u ^= (u & 0x80000000u) ? 0xFFFFFFFFu : 0x80000000u;
        unsigned h = ~u;
        int b = ga / TOTAL;
        int i_loc = ga - b * TOTAL;
        unsigned long long key = ((unsigned long long)h << 32) |
                                 ((unsigned)(i_loc << 7) | (unsigned)bi);
        if (i_loc >= 21504) {            // levels 3,4: selected unconditionally
            bucket_push(b, key);
        } else {
            d_keys[ga] = key;
            int lvl = (i_loc < 16384) ? 0 : (i_loc < 20480) ? 1 : 2;
            atomicAdd(&d_hist[(b * 3 + lvl) * BINN + qbin(h)], 1);
        }
    }
}

// ---------------- K2: per (batch, level 0..2) exact top-k; hist prebuilt ---------------
// Scan hist -> boundary bin Q + kneed; ONE sweep: push bins>Q, collect boundary bin;
// exact in-bin rank pushes the kneed smallest boundary keys. Exact incl. ties.
__global__ __launch_bounds__(1024, 1) void k_select() {
    const int LOFF[3] = {0, 16384, 20480};
    const int LN[3]   = {16384, 4096, 1024};
    const int LK[3]   = {1000, 1000, 1000};

    int b = blockIdx.x / 3, lvl = blockIdx.x % 3;
    int off = LOFF[lvl], n = LN[lvl], k = LK[lvl];
    int tid = threadIdx.x, lane = tid & 31, wid = tid >> 5;
    const unsigned long long* kp = d_keys + b * TOTAL + off;

    __shared__ unsigned long long binkeys[BCAP];
    __shared__ int warpsum[32];
    __shared__ int sh_Q, sh_kneed, sh_bc;
    if (tid == 0) sh_bc = 0;
    __syncthreads();

    const int* hist = d_hist + (b * 3 + lvl) * BINN;

    // descending-bin cumulative scan (4 bins/thread): boundary bin Q, kneed
    {
        int vv[4], mysum = 0;
#pragma unroll
        for (int j = 0; j < 4; j++) { vv[j] = hist[BINN - 1 - (tid * 4 + j)]; mysum += vv[j]; }
        int inc = mysum;
#pragma unroll
        for (int o = 1; o < 32; o <<= 1) { int t2 = __shfl_up_sync(0xFFFFFFFFu, inc, o); if (lane >= o) inc += t2; }
        if (lane == 31) warpsum[wid] = inc;
        __syncthreads();
        if (tid < 32) {
            int w = warpsum[tid], s = w;
#pragma unroll
            for (int o = 1; o < 32; o <<= 1) { int t2 = __shfl_up_sync(0xFFFFFFFFu, s, o); if (tid >= o) s += t2; }
            warpsum[tid] = s - w;  // exclusive
        }
        __syncthreads();
        int c = warpsum[wid] + inc - mysum;
#pragma unroll
        for (int j = 0; j < 4; j++) {
            if (c < k && c + vv[j] >= k) {
                sh_Q = BINN - 1 - (tid * 4 + j);
                sh_kneed = k - c;
            }
            c += vv[j];
        }
    }
    __syncthreads();
    int Q = sh_Q, kneed = sh_kneed;

    // single sweep: push bins > Q to class buckets; collect boundary bin
    for (int i = tid; i < n; i += 1024) {
        unsigned long long key = kp[i];
        int q = qbin((unsigned)(key >> 32));
        if (q > Q) {
            bucket_push(b, key);
        } else if (q == Q) {
            int p = atomicAdd(&sh_bc, 1);
            if (p < BCAP) binkeys[p] = key;
        }
    }
    __syncthreads();
    int C = min(sh_bc, BCAP);

    // exact in-bin rank; push the kneed smallest boundary keys (keys distinct)
    for (int t = tid; t < C; t += 1024) {
        unsigned long long mk = binkeys[t];
        int r = 0;
        for (int j2 = 0; j2 < C; j2++) r += (binkeys[j2] < mk);
        if (r < kneed) bucket_push(b, mk);
    }
}

// ---------------- K3: one warp per (batch,class): sort, NMS, append + survivor hist ----
__global__ __launch_bounds__(32) void k_nms(const float* __restrict__ reg,
                                            const float* __restrict__ anchors) {
    int bc = blockIdx.x, b = bc / 80;
    __shared__ unsigned long long kb[MAXB];
    __shared__ float4 bxs[MAXB];
    __shared__ float  ar[MAXB], sv[MAXB];
    __shared__ unsigned char rm[MAXB];
    int lane = threadIdx.x;

    // restore d_hist to zero for the next call (select is done with it)
    {
        const int totalH = BATCH * 3 * BINN;
        int per = (totalH + 639) / 640;   // grid is 640
        int s0 = bc * per, s1 = min(s0 + per, totalH);
        for (int i = s0 + lane; i < s1; i += 32) d_hist[i] = 0;
    }

    int cnt = min(d_ccnt[bc], MAXB);
    if (cnt == 0) return;
    for (int i = lane; i < cnt; i += 32)
        kb[i] = d_bucket[(size_t)bc * MAXB + i];
    __syncwarp();

    // warp bitonic sort ascending (== score desc, idx asc)
    int m = 2; while (m < cnt) m <<= 1;
    for (int i = lane; i < m; i += 32) if (i >= cnt) kb[i] = ~0ULL;
    __syncwarp();
    for (int kk = 2; kk <= m; kk <<= 1)
        for (int jj = kk >> 1; jj > 0; jj >>= 1) {
            for (int cc = lane; cc < (m >> 1); cc += 32) {
                int i1 = ((cc & ~(jj - 1)) << 1) | (cc & (jj - 1));
                int l1 = i1 | jj;
                bool up = ((i1 & kk) == 0);
                unsigned long long a2 = kb[i1], d2 = kb[l1];
                if ((a2 > d2) == up) { kb[i1] = d2; kb[l1] = a2; }
            }
            __syncwarp();
        }

    // decode
    for (int i = lane; i < cnt; i += 32) {
        unsigned long long key = kb[i];
        int idx = (int)((key >> 7) & 0x7FFFULL);
        sv[i] = key_score(key);
        rm[i] = 0;
        float4 an = reinterpret_cast<const float4*>(anchors)[idx];
        float cx = (an.x + an.z) * 0.5f, cy = (an.y + an.w) * 0.5f;
        float4 r = reinterpret_cast<const float4*>(reg)[(size_t)b * TOTAL + idx];
        float x1 = fminf(fmaxf(cx - r.x, 0.0f), IMGF);
        float y1 = fminf(fmaxf(cy - r.y, 0.0f), IMGF);
        float x2 = fminf(fmaxf(cx + r.z, 0.0f), IMGF);
        float y2 = fminf(fmaxf(cy + r.w, 0.0f), IMGF);
        bxs[i] = make_float4(x1, y1, x2, y2);
        ar[i] = fmaxf(x2 - x1, 0.0f) * fmaxf(y2 - y1, 0.0f);
    }
    __syncwarp();

    // greedy NMS (masked sort last; suppressed never suppress)
    for (int i = 0; i < cnt; i++) {
        if (sv[i] <= STH) break;
        if (rm[i]) continue;
        float4 bi = bxs[i];
        float ai = ar[i];
        for (int j = i + 1 + lane; j < cnt; j += 32) {
            float4 bj = bxs[j];
            float iw = fmaxf(fminf(bi.z, bj.z) - fmaxf(bi.x, bj.x), 0.0f);
            float ih = fmaxf(fminf(bi.w, bj.w) - fmaxf(bi.y, bj.y), 0.0f);
            float inter = iw * ih;
            float iou = inter / fmaxf(ai + ar[j] - inter, 1e-9f);
            if (iou > NMST) rm[j] = 1;
        }
        __syncwarp();
    }

    // append survivors (per-class cap DETS) + survivor histogram
    int wcnt = 0;
    for (int base = 0; base < cnt; base += 32) {
        int i = base + lane;
        bool acc = (i < cnt) && (sv[i] > STH) && !rm[i];
        unsigned bal = __ballot_sync(0xFFFFFFFFu, acc);
        int nb = __popc(bal);
        int nTake = min(nb, max(0, DETS - wcnt));
        int pos = 0;
        if (lane == 0 && nTake > 0) pos = atomicAdd(&d_surtot[b], nTake);
        pos = __shfl_sync(0xFFFFFFFFu, pos, 0);
        int rk = __popc(bal & ((1u << lane) - 1));
        if (acc && rk < nTake && pos + rk < SCAP) {
            d_sur[(size_t)b * SCAP + pos + rk] = kb[i];
            atomicAdd(&d_ohist[b * BINN + qbin((unsigned)(kb[i] >> 32))], 1);
        }
        wcnt += nb;
    }
}

// ---------------- K4: per-batch top-100; survivor hist prebuilt by k_nms ----------------
__global__ __launch_bounds__(1024, 1) void k_out(const float* __restrict__ reg,
                                                 const float* __restrict__ anchors,
                                                 float* __restrict__ out) {
    __shared__ unsigned long long cont[OCAP];
    __shared__ unsigned long long win[DETS];
    __shared__ int warpsum[32];
    __shared__ int sh_cc, sh_Q;

    int b = blockIdx.x, tid = threadIdx.x, lane = tid & 31, wid = tid >> 5;

    int S = min(d_surtot[b], SCAP);
    int ns = min(DETS, S);
    if (tid == 0) { sh_cc = 0; sh_Q = 0; }
    __syncthreads();

    const int* hist = d_ohist + b * BINN;

    if (ns > 0) {
        // descending-bin scan: first bin where cum >= ns
        int vv[4], mysum = 0;
#pragma unroll
        for (int j = 0; j < 4; j++) { vv[j] = hist[BINN - 1 - (tid * 4 + j)]; mysum += vv[j]; }
        int inc = mysum;
#pragma unroll
        for (int o = 1; o < 32; o <<= 1) { int t2 = __shfl_up_sync(0xFFFFFFFFu, inc, o); if (lane >= o) inc += t2; }
        if (lane == 31) warpsum[wid] = inc;
        __syncthreads();
        if (tid < 32) {
            int w = warpsum[tid], s = w;
#pragma unroll
            for (int o = 1; o < 32; o <<= 1) { int t2 = __shfl_up_sync(0xFFFFFFFFu, s, o); if (tid >= o) s += t2; }
            warpsum[tid] = s - w;
        }
        __syncthreads();
        int c = warpsum[wid] + inc - mysum;
#pragma unroll
        for (int j = 0; j < 4; j++) {
            if (c < ns && c + vv[j] >= ns) sh_Q = BINN - 1 - (tid * 4 + j);
            c += vv[j];
        }
        __syncthreads();
        int Q = sh_Q;

        // single sweep: contention = all bins >= Q (superset of top-ns)
        for (int i = tid; i < S; i += 1024) {
            unsigned long long key = d_sur[(size_t)b * SCAP + i];
            if (qbin((unsigned)(key >> 32)) >= Q) {
                int p = atomicAdd(&sh_cc, 1);
                if (p < OCAP) cont[p] = key;
            }
        }
        __syncthreads();
        int C = min(sh_cc, OCAP);

        // exact rank within contention == global rank for r < ns
        for (int t = tid; t < C; t += 1024) {
            unsigned long long mk = cont[t];
            int r = 0;
            for (int q2 = 0; q2 < C; q2++) r += (cont[q2] < mk);
            if (r < ns) win[r] = mk;
        }
    }
    __syncthreads();

    // decode + write
    for (int t = tid; t < DETS; t += 1024) {
        float* ob = out + ((size_t)b * DETS + t) * 4;
        if (t >= ns) {
            ob[0] = 0.0f; ob[1] = 0.0f; ob[2] = 0.0f; ob[3] = 0.0f;
            out[BATCH * DETS * 4 + b * DETS + t] = 0.0f;
            out[BATCH * DETS * 5 + b * DETS + t] = -1.0f;
        } else {
            unsigned long long key = win[t];
            int idx = (int)((key >> 7) & 0x7FFFULL);
            float4 an = reinterpret_cast<const float4*>(anchors)[idx];
            float cx = (an.x + an.z) * 0.5f, cy = (an.y + an.w) * 0.5f;
            float4 r = reinterpret_cast<const float4*>(reg)[(size_t)b * TOTAL + idx];
            float x1 = fminf(fmaxf(cx - r.x, 0.0f), IMGF);
            float y1 = fminf(fmaxf(cy - r.y, 0.0f), IMGF);
            float x2 = fminf(fmaxf(cx + r.z, 0.0f), IMGF);
            float y2 = fminf(fmaxf(cy + r.w, 0.0f), IMGF);
            ob[0] = x1; ob[1] = y1; ob[2] = x2; ob[3] = y2;
            out[BATCH * DETS * 4 + b * DETS + t] = key_score(key);
            out[BATCH * DETS * 5 + b * DETS + t] = (float)(key & 127ULL);
        }
    }
    __syncthreads();

    // restore per-batch scratch to zero for the next call
    for (int i = tid; i < BINN; i += 1024) d_ohist[b * BINN + i] = 0;
    for (int i = tid; i < 80; i += 1024) d_ccnt[b * 80 + i] = 0;
    if (tid == 0) d_surtot[b] = 0;
}

// ---------------- launch ----------------
extern "C" void kernel_launch(void* const* d_in, const int* in_sizes, int n_in,
                              void* d_out, int out_size) {
    const float* logits  = (const float*)d_in[0];  // (8, 21824, 80)
    const float* reg     = (const float*)d_in[1];  // (8, 21824, 4)
    const float* ctr     = (const float*)d_in[2];  // (8, 21824, 1)
    const float* anchors = (const float*)d_in[3];  // (21824, 4)
    float* out = (float*)d_out;

    k_score<<<(BATCH * TOTAL) / 128, 512>>>(logits, ctr);
    k_select<<<BATCH * 3, 1024>>>();
    k_nms<<<BATCH * 80, 32>>>(reg, anchors);
    k_out<<<BATCH, 1024>>>(reg, anchors, out);
}

// round 15
// speedup vs baseline: 1.8649x; 1.4892x over previous
#include <cuda_runtime.h>
#include <math.h>
#include <stdint.h>

#define BATCH 8
#define TOTAL 21824
#define DETS  100
#define IMGF  1024.0f
#define STH   0.2f
#define NMST  0.6f
#define MAXB  128    // per-class bucket capacity (mean ~41, 13-sigma safe)
#define BINN  4096   // quantization bins
#define BCAP  512    // boundary-bin capacity (expected ~16)
#define OCAP  1024   // out contention capacity (expected ~110)
#define SCAP  3328   // compact survivor capacity per batch (max possible 3320)

// ---------------- scratch ----------------
__device__ unsigned long long d_keys[BATCH * TOTAL];
__device__ unsigned long long d_bucket[BATCH * 80 * MAXB];
__device__ int                d_ccnt[BATCH * 80];
__device__ unsigned long long d_sur[BATCH * SCAP];
__device__ int                d_surtot[BATCH];
__device__ int                d_ohist[BATCH * BINN];   // survivor hist (fed by k_nms)

__device__ __forceinline__ float sigf(float x) { return 1.0f / (1.0f + expf(-x)); }

__device__ __forceinline__ float key_score_hi(unsigned h) {
    unsigned uo = ~h;
    unsigned bits = (uo & 0x80000000u) ? (uo ^ 0x80000000u) : (~uo);
    return __uint_as_float(bits);
}
__device__ __forceinline__ float key_score(unsigned long long key) {
    return key_score_hi((unsigned)(key >> 32));
}
// monotone: higher score -> higher bin; masked (-1) -> bin 0
__device__ __forceinline__ int qbin(unsigned h) {
    float s = key_score_hi(h);
    return (s > 0.0f) ? min(BINN - 1, (int)(s * (float)BINN)) : 0;
}

__device__ __forceinline__ void bucket_push(int b, unsigned long long key) {
    int c = (int)(key & 127ULL);
    int pos = atomicAdd(&d_ccnt[b * 80 + c], 1);
    if (pos < MAXB) d_bucket[(size_t)(b * 80 + c) * MAXB + pos] = key;
}

// ---------------- K1: staged coalesced score + argmax -> 64-bit key ----------------
// key = (~orderable(score))<<32 | idx<<7 | label : ascending == (score desc, idx asc);
// keys globally distinct; matches jax.lax.top_k stable tie order.
__global__ __launch_bounds__(512) void k_score(const float* __restrict__ logits,
                                               const float* __restrict__ ctr) {
    __shared__ float4 s4[128 * 20];  // 40 KB
    int tid = threadIdx.x;
    if (blockIdx.x == 0) {
        for (int i = tid; i < BATCH * 80; i += 512) d_ccnt[i] = 0;
        if (tid < BATCH) d_surtot[tid] = 0;
        for (int i = tid; i < BATCH * BINN; i += 512) d_ohist[i] = 0;
    }
    const float4* g = reinterpret_cast<const float4*>(logits) + (size_t)blockIdx.x * (128 * 20);
#pragma unroll
    for (int i = 0; i < 5; i++) s4[i * 512 + tid] = __ldcs(&g[i * 512 + tid]);
    __syncthreads();

    int la = tid >> 2;   // local anchor 0..127
    int q  = tid & 3;    // quarter: cols 20q..20q+19
    const float4* rowq = s4 + la * 20 + q * 5;
    float best = -1e30f;
    int bi = 0;
#pragma unroll
    for (int i = 0; i < 5; i++) {  // strict > keeps first-max within lane
        float4 v = rowq[i];
        int cb = q * 20 + i * 4;
        if (v.x > best) { best = v.x; bi = cb + 0; }
        if (v.y > best) { best = v.y; bi = cb + 1; }
        if (v.z > best) { best = v.z; bi = cb + 2; }
        if (v.w > best) { best = v.w; bi = cb + 3; }
    }
#pragma unroll
    for (int o = 2; o >= 1; o >>= 1) {  // tie -> lower column (= first occurrence)
        float ov = __shfl_down_sync(0xFFFFFFFFu, best, o);
        int   oc = __shfl_down_sync(0xFFFFFFFFu, bi, o);
        if (ov > best || (ov == best && oc < bi)) { best = ov; bi = oc; }
    }
    if (q == 0) {
        int ga = blockIdx.x * 128 + la;   // BATCH*TOTAL % 128 == 0
        float s = sqrtf(sigf(best) * sigf(ctr[ga]));
        float sm = (s > STH) ? s : -1.0f;
        unsigned u = __float_as_uint(sm);
        u ^= (u & 0x80000000u) ? 0xFFFFFFFFu : 0x80000000u;
        int i_loc = ga % TOTAL;
        d_keys[ga] = ((unsigned long long)(~u) << 32) |
                     ((unsigned)(i_loc << 7) | (unsigned)bi);
    }
}

// ---------------- K2: per (batch, level) exact top-k via quantized bins --------------
// Sweep 1 (global): stage keys to SMEM + 4096-bin histogram (plain spread atomics).
// Scan: boundary bin Q + kneed. Sweep 2 (SMEM): push bins>Q to class buckets, collect
// boundary bin. Rank: push kneed smallest boundary keys. Exact incl. ties.
#define SEL_SMEM (131072 + BINN * 4 + BCAP * 8)   // hi/lo 128K | hist 16K | binkeys 4K

__global__ __launch_bounds__(1024, 1) void k_select() {
    extern __shared__ unsigned char smraw[];
    const int LOFF[5] = {0, 16384, 20480, 21504, 21760};
    const int LN[5]   = {16384, 4096, 1024, 256, 64};
    const int LK[5]   = {1000, 1000, 1000, 256, 64};

    int b = blockIdx.x / 5, lvl = blockIdx.x % 5;
    int off = LOFF[lvl], n = LN[lvl], k = LK[lvl];
    int tid = threadIdx.x, lane = tid & 31, wid = tid >> 5;
    const unsigned long long* kp = d_keys + b * TOTAL + off;

    if (k >= n) {  // levels 3,4: everything selected
        for (int i = tid; i < n; i += 1024) bucket_push(b, kp[i]);
        return;
    }

    unsigned* hi = (unsigned*)smraw;
    unsigned* lo = hi + n;
    unsigned* hist = (unsigned*)(smraw + 131072);
    unsigned long long* binkeys = (unsigned long long*)(smraw + 131072 + BINN * 4);
    __shared__ int warpsum[32];
    __shared__ int sh_Q, sh_kneed, sh_bc;

    for (int i = tid; i < BINN; i += 1024) hist[i] = 0;
    if (tid == 0) sh_bc = 0;
    __syncthreads();

    // sweep 1: stage + histogram (no warp-sync ops -> load latency pipelines)
    for (int i = tid; i < n; i += 1024) {
        unsigned long long key = kp[i];
        unsigned h = (unsigned)(key >> 32);
        hi[i] = h;
        lo[i] = (unsigned)key;
        atomicAdd(&hist[qbin(h)], 1u);
    }
    __syncthreads();

    // descending-bin cumulative scan (4 bins/thread): boundary bin Q, kneed
    {
        int vv[4], mysum = 0;
#pragma unroll
        for (int j = 0; j < 4; j++) { vv[j] = hist[BINN - 1 - (tid * 4 + j)]; mysum += vv[j]; }
        int inc = mysum;
#pragma unroll
        for (int o = 1; o < 32; o <<= 1) { int t2 = __shfl_up_sync(0xFFFFFFFFu, inc, o); if (lane >= o) inc += t2; }
        if (lane == 31) warpsum[wid] = inc;
        __syncthreads();
        if (tid < 32) {
            int w = warpsum[tid], s = w;
#pragma unroll
            for (int o = 1; o < 32; o <<= 1) { int t2 = __shfl_up_sync(0xFFFFFFFFu, s, o); if (tid >= o) s += t2; }
            warpsum[tid] = s - w;  // exclusive
        }
        __syncthreads();
        int c = warpsum[wid] + inc - mysum;
#pragma unroll
        for (int j = 0; j < 4; j++) {
            if (c < k && c + vv[j] >= k) {
                sh_Q = BINN - 1 - (tid * 4 + j);
                sh_kneed = k - c;
            }
            c += vv[j];
        }
    }
    __syncthreads();
    int Q = sh_Q, kneed = sh_kneed;

    // sweep 2 (SMEM): push bins > Q; collect boundary bin
    for (int i = tid; i < n; i += 1024) {
        unsigned h = hi[i];
        int q = qbin(h);
        if (q > Q) {
            bucket_push(b, ((unsigned long long)h << 32) | lo[i]);
        } else if (q == Q) {
            int p = atomicAdd(&sh_bc, 1);
            if (p < BCAP) binkeys[p] = ((unsigned long long)h << 32) | lo[i];
        }
    }
    __syncthreads();
    int C = min(sh_bc, BCAP);

    // exact in-bin rank; push the kneed smallest boundary keys (keys distinct)
    for (int t = tid; t < C; t += 1024) {
        unsigned long long mk = binkeys[t];
        int r = 0;
        for (int j2 = 0; j2 < C; j2++) r += (binkeys[j2] < mk);
        if (r < kneed) bucket_push(b, mk);
    }
}

// ---------------- K3: one warp per (batch,class): sort bucket, NMS, compact append ----
__global__ __launch_bounds__(32) void k_nms(const float* __restrict__ reg,
                                            const float* __restrict__ anchors) {
    int bc = blockIdx.x, b = bc / 80;
    __shared__ unsigned long long kb[MAXB];
    __shared__ float4 bxs[MAXB];
    __shared__ float  ar[MAXB], sv[MAXB];
    __shared__ unsigned char rm[MAXB];
    int lane = threadIdx.x;

    int cnt = min(d_ccnt[bc], MAXB);
    if (cnt == 0) return;
    for (int i = lane; i < cnt; i += 32)
        kb[i] = d_bucket[(size_t)bc * MAXB + i];
    __syncwarp();

    // warp bitonic sort ascending (== score desc, idx asc)
    int m = 2; while (m < cnt) m <<= 1;
    for (int i = lane; i < m; i += 32) if (i >= cnt) kb[i] = ~0ULL;
    __syncwarp();
    for (int kk = 2; kk <= m; kk <<= 1)
        for (int jj = kk >> 1; jj > 0; jj >>= 1) {
            for (int cc = lane; cc < (m >> 1); cc += 32) {
                int i1 = ((cc & ~(jj - 1)) << 1) | (cc & (jj - 1));
                int l1 = i1 | jj;
                bool up = ((i1 & kk) == 0);
                unsigned long long a2 = kb[i1], d2 = kb[l1];
                if ((a2 > d2) == up) { kb[i1] = d2; kb[l1] = a2; }
            }
            __syncwarp();
        }

    // decode
    for (int i = lane; i < cnt; i += 32) {
        unsigned long long key = kb[i];
        int idx = (int)((key >> 7) & 0x7FFFULL);
        sv[i] = key_score(key);
        rm[i] = 0;
        float4 an = reinterpret_cast<const float4*>(anchors)[idx];
        float cx = (an.x + an.z) * 0.5f, cy = (an.y + an.w) * 0.5f;
        float4 r = reinterpret_cast<const float4*>(reg)[(size_t)b * TOTAL + idx];
        float x1 = fminf(fmaxf(cx - r.x, 0.0f), IMGF);
        float y1 = fminf(fmaxf(cy - r.y, 0.0f), IMGF);
        float x2 = fminf(fmaxf(cx + r.z, 0.0f), IMGF);
        float y2 = fminf(fmaxf(cy + r.w, 0.0f), IMGF);
        bxs[i] = make_float4(x1, y1, x2, y2);
        ar[i] = fmaxf(x2 - x1, 0.0f) * fmaxf(y2 - y1, 0.0f);
    }
    __syncwarp();

    // greedy NMS (masked sort last; suppressed never suppress)
    for (int i = 0; i < cnt; i++) {
        if (sv[i] <= STH) break;
        if (rm[i]) continue;
        float4 bi = bxs[i];
        float ai = ar[i];
        for (int j = i + 1 + lane; j < cnt; j += 32) {
            float4 bj = bxs[j];
            float iw = fmaxf(fminf(bi.z, bj.z) - fmaxf(bi.x, bj.x), 0.0f);
            float ih = fmaxf(fminf(bi.w, bj.w) - fmaxf(bi.y, bj.y), 0.0f);
            float inter = iw * ih;
            float iou = inter / fmaxf(ai + ar[j] - inter, 1e-9f);
            if (iou > NMST) rm[j] = 1;
        }
        __syncwarp();
    }

    // append survivors (per-class cap DETS) + survivor histogram
    int wcnt = 0;
    for (int base = 0; base < cnt; base += 32) {
        int i = base + lane;
        bool acc = (i < cnt) && (sv[i] > STH) && !rm[i];
        unsigned bal = __ballot_sync(0xFFFFFFFFu, acc);
        int nb = __popc(bal);
        int nTake = min(nb, max(0, DETS - wcnt));
        int pos = 0;
        if (lane == 0 && nTake > 0) pos = atomicAdd(&d_surtot[b], nTake);
        pos = __shfl_sync(0xFFFFFFFFu, pos, 0);
        int rk = __popc(bal & ((1u << lane) - 1));
        if (acc && rk < nTake && pos + rk < SCAP) {
            d_sur[(size_t)b * SCAP + pos + rk] = kb[i];
            atomicAdd(&d_ohist[b * BINN + qbin((unsigned)(kb[i] >> 32))], 1);
        }
        wcnt += nb;
    }
}

// ---------------- K4: per-batch top-100; survivor hist prebuilt by k_nms ----------------
__global__ __launch_bounds__(1024, 1) void k_out(const float* __restrict__ reg,
                                                 const float* __restrict__ anchors,
                                                 float* __restrict__ out) {
    __shared__ unsigned long long cont[OCAP];
    __shared__ unsigned long long win[DETS];
    __shared__ int warpsum[32];
    __shared__ int sh_cc, sh_Q;

    int b = blockIdx.x, tid = threadIdx.x, lane = tid & 31, wid = tid >> 5;

    int S = min(d_surtot[b], SCAP);
    int ns = min(DETS, S);
    if (tid == 0) { sh_cc = 0; sh_Q = 0; }
    __syncthreads();

    const int* hist = d_ohist + b * BINN;

    if (ns > 0) {
        // descending-bin scan: first bin where cum >= ns
        int vv[4], mysum = 0;
#pragma unroll
        for (int j = 0; j < 4; j++) { vv[j] = hist[BINN - 1 - (tid * 4 + j)]; mysum += vv[j]; }
        int inc = mysum;
#pragma unroll
        for (int o = 1; o < 32; o <<= 1) { int t2 = __shfl_up_sync(0xFFFFFFFFu, inc, o); if (lane >= o) inc += t2; }
        if (lane == 31) warpsum[wid] = inc;
        __syncthreads();
        if (tid < 32) {
            int w = warpsum[tid], s = w;
#pragma unroll
            for (int o = 1; o < 32; o <<= 1) { int t2 = __shfl_up_sync(0xFFFFFFFFu, s, o); if (tid >= o) s += t2; }
            warpsum[tid] = s - w;
        }
        __syncthreads();
        int c = warpsum[wid] + inc - mysum;
#pragma unroll
        for (int j = 0; j < 4; j++) {
            if (c < ns && c + vv[j] >= ns) sh_Q = BINN - 1 - (tid * 4 + j);
            c += vv[j];
        }
        __syncthreads();
        int Q = sh_Q;

        // single sweep over compact survivors: contention = all bins >= Q
        for (int i = tid; i < S; i += 1024) {
            unsigned long long key = d_sur[(size_t)b * SCAP + i];
            if (qbin((unsigned)(key >> 32)) >= Q) {
                int p = atomicAdd(&sh_cc, 1);
                if (p < OCAP) cont[p] = key;
            }
        }
        __syncthreads();
        int C = min(sh_cc, OCAP);

        // exact rank within contention == global rank for r < ns
        for (int t = tid; t < C; t += 1024) {
            unsigned long long mk = cont[t];
            int r = 0;
            for (int q2 = 0; q2 < C; q2++) r += (cont[q2] < mk);
            if (r < ns) win[r] = mk;
        }
    }
    __syncthreads();

    // decode + write
    for (int t = tid; t < DETS; t += 1024) {
        float* ob = out + ((size_t)b * DETS + t) * 4;
        if (t >= ns) {
            ob[0] = 0.0f; ob[1] = 0.0f; ob[2] = 0.0f; ob[3] = 0.0f;
            out[BATCH * DETS * 4 + b * DETS + t] = 0.0f;
            out[BATCH * DETS * 5 + b * DETS + t] = -1.0f;
        } else {
            unsigned long long key = win[t];
            int idx = (int)((key >> 7) & 0x7FFFULL);
            float4 an = reinterpret_cast<const float4*>(anchors)[idx];
            float cx = (an.x + an.z) * 0.5f, cy = (an.y + an.w) * 0.5f;
            float4 r = reinterpret_cast<const float4*>(reg)[(size_t)b * TOTAL + idx];
            float x1 = fminf(fmaxf(cx - r.x, 0.0f), IMGF);
            float y1 = fminf(fmaxf(cy - r.y, 0.0f), IMGF);
            float x2 = fminf(fmaxf(cx + r.z, 0.0f), IMGF);
            float y2 = fminf(fmaxf(cy + r.w, 0.0f), IMGF);
            ob[0] = x1; ob[1] = y1; ob[2] = x2; ob[3] = y2;
            out[BATCH * DETS * 4 + b * DETS + t] = key_score(key);
            out[BATCH * DETS * 5 + b * DETS + t] = (float)(key & 127ULL);
        }
    }
}

// ---------------- launch ----------------
extern "C" void kernel_launch(void* const* d_in, const int* in_sizes, int n_in,
                              void* d_out, int out_size) {
    const float* logits  = (const float*)d_in[0];  // (8, 21824, 80)
    const float* reg     = (const float*)d_in[1];  // (8, 21824, 4)
    const float* ctr     = (const float*)d_in[2];  // (8, 21824, 1)
    const float* anchors = (const float*)d_in[3];  // (21824, 4)
    float* out = (float*)d_out;

    cudaFuncSetAttribute(k_select, cudaFuncAttributeMaxDynamicSharedMemorySize, SEL_SMEM);

    k_score<<<(BATCH * TOTAL) / 128, 512>>>(logits, ctr);
    k_select<<<BATCH * 5, 1024, SEL_SMEM>>>();
    k_nms<<<BATCH * 80, 32>>>(reg, anchors);
    k_out<<<BATCH, 1024>>>(reg, anchors, out);
}